// round 12
// baseline (speedup 1.0000x reference)
#include <cuda_runtime.h>

#define HID 128
#define INP 33
#define OUTD 3
#define TT 2000
#define BATCH 256

typedef unsigned long long u64;

// Packed fp32x2 FMA (FFMA2) — only reachable via PTX fma.rn.f32x2.
__device__ __forceinline__ u64 ffma2(u64 a, u64 b, u64 c) {
    u64 d;
    asm("fma.rn.f32x2 %0, %1, %2, %3;" : "=l"(d) : "l"(a), "l"(b), "l"(c));
    return d;
}
__device__ __forceinline__ float2 unpack2(u64 v) {
    float2 f;
    asm("mov.b64 {%0, %1}, %2;" : "=f"(f.x), "=f"(f.y) : "l"(v));
    return f;
}
__device__ __forceinline__ u64 pack2(float x, float y) {
    u64 v;
    asm("mov.b64 %0, {%1, %2};" : "=l"(v) : "f"(x), "f"(y));
    return v;
}

// Accurate tanh via __expf (MUFU): rel err ~1e-6 (tanh.approx's 6e-4 is unsafe
// over a 2000-step recurrence).
__device__ __forceinline__ float fast_tanh(float x) {
    float ax = fabsf(x);
    float e = __expf(2.0f * fminf(ax, 10.0f));
    float t = 1.0f - 2.0f / (e + 1.0f);
    return copysignf(t, x);
}

// ---------------------------------------------------------------------------
// Pass 1: input projection, in-place into the hidden output buffer.
// DOUBLE-BUFFERED x staging: one barrier per tile; the next tile's gmem loads
// issue before the compute of the current tile, so load latency overlaps
// (fixes R11's issue=37% / exposed-LDG limiter). 592 CTAs = 4/SM.
// ---------------------------------------------------------------------------
#define PR 32

__global__ void __launch_bounds__(256)
proj_kernel(const float* __restrict__ x,
            const float* __restrict__ W_in,
            const float* __restrict__ b_in,
            float* __restrict__ proj)
{
    __shared__ __align__(16) float xs[2][PR][34];

    const int tid  = threadIdx.x;
    const int j    = tid & 127;
    const int half = tid >> 7;

    // W_in row j -> 17 packed pairs (last = (w32, 0))
    u64 wi[17];
    {
        float wv[34];
        #pragma unroll
        for (int i = 0; i < INP; i++) wv[i] = W_in[j * INP + i];
        wv[33] = 0.0f;
        #pragma unroll
        for (int i = 0; i < 17; i++) wi[i] = pack2(wv[2 * i], wv[2 * i + 1]);
    }
    const float bj = b_in[j];

    if (tid < PR) { xs[0][tid][33] = 0.0f; xs[1][tid][33] = 0.0f; }  // pads, once

    const int ntiles = (BATCH * TT) / PR;   // 16000
    int tile = blockIdx.x;

    // Preload first tile into buffer 0.
    {
        const float* xsrc = x + (long)tile * PR * INP;
        for (int idx = tid; idx < PR * INP; idx += 256) {
            int r = idx / INP, i = idx - r * INP;
            xs[0][r][i] = xsrc[idx];
        }
    }
    __syncthreads();

    int buf = 0;
    while (tile < ntiles) {
        const int next = tile + gridDim.x;
        if (next < ntiles) {                       // prefetch next tile (other buf)
            const float* xsrc = x + (long)next * PR * INP;
            for (int idx = tid; idx < PR * INP; idx += 256) {
                int r = idx / INP, i = idx - r * INP;
                xs[buf ^ 1][r][i] = xsrc[idx];
            }
        }

        const long base = (long)tile * PR;
        #pragma unroll 4
        for (int rr = 0; rr < 16; rr++) {
            int r = half * 16 + rr;
            const u64* xp = (const u64*)xs[buf][r];
            u64 acc[4] = {0ull, 0ull, 0ull, 0ull};
            #pragma unroll
            for (int i = 0; i < 17; i++)
                acc[i & 3] = ffma2(wi[i], xp[i], acc[i & 3]);
            float2 f0 = unpack2(acc[0]), f1 = unpack2(acc[1]);
            float2 f2 = unpack2(acc[2]), f3 = unpack2(acc[3]);
            float s = ((f0.x + f1.x) + (f2.x + f3.x))
                    + ((f0.y + f1.y) + (f2.y + f3.y)) + bj;
            proj[(base + r) * HID + j] = s;        // coalesced per warp-group
        }

        __syncthreads();                           // next buf ready; xs[buf] free
        buf ^= 1;
        tile = next;
    }
}

// ---------------------------------------------------------------------------
// Pass 2: serial recurrence (R5's proven core: 1 batch row per CTA, 256 CTAs,
// 2 CTAs/SM -> 2 warps/SMSP for cross-warp latency hiding) PLUS a fused
// readout warp. Threads 0-127: recurrence exactly as R5. Threads 128-159:
// after each step's barrier, read the just-computed h[t] from smem, compute
// the 3-way dot with W_out (butterfly reduce), store pred[b,t,:]. This
// deletes the separate readout kernel and its 262 MB hidden re-read.
// ---------------------------------------------------------------------------
__global__ void __launch_bounds__(160, 2)
rnn_recurrence_kernel(const float* __restrict__ W_rec,
                      const float* __restrict__ W_out,
                      const float* __restrict__ b_out,
                      float* __restrict__ hidden /* in: proj, out: h */,
                      float* __restrict__ pred)
{
    __shared__ __align__(16) float hbuf[2][HID];

    const int j = threadIdx.x;
    const int b = blockIdx.x;

    // ---- recurrence-warp state (threads 0..127) ----
    u64 w[64];
    float hj = 0.0f, p_cur = 0.0f, p_nxt = 0.0f;
    float* pj = hidden + (size_t)b * TT * HID + j;
    if (j < HID) {
        const ulonglong2* wrow = (const ulonglong2*)(W_rec + j * HID);
        #pragma unroll
        for (int k = 0; k < 32; k++) {
            ulonglong2 v = wrow[k];
            w[2 * k]     = v.x;
            w[2 * k + 1] = v.y;
        }
        hbuf[0][j] = 0.0f;
        p_cur = __ldg(pj);
        p_nxt = __ldg(pj + HID);
    }

    // ---- readout-warp state (threads 128..159) ----
    const int lane = j - HID;
    float4 w0, w1, w2;
    float bo0 = 0.f, bo1 = 0.f, bo2 = 0.f;
    float* po = pred + (size_t)b * TT * OUTD;
    if (j >= HID) {
        const float4* w4 = (const float4*)W_out;
        w0 = __ldg(&w4[lane]);
        w1 = __ldg(&w4[32 + lane]);
        w2 = __ldg(&w4[64 + lane]);
        bo0 = __ldg(&b_out[0]); bo1 = __ldg(&b_out[1]); bo2 = __ldg(&b_out[2]);
    }

    __syncthreads();

    int p = 0;
    for (int t = 0; t < TT; t++) {
        if (j < HID) {
            float p_fut = 0.0f;
            if (t + 2 < TT) p_fut = __ldg(pj + (size_t)(t + 2) * HID);

            const ulonglong2* hs = (const ulonglong2*)hbuf[p];
            u64 acc[4] = {0ull, 0ull, 0ull, 0ull};

            #pragma unroll
            for (int k = 0; k < 32; k++) {
                ulonglong2 hh = hs[k];                       // broadcast LDS.128
                acc[(2 * k)     & 3] = ffma2(w[2 * k],     hh.x, acc[(2 * k)     & 3]);
                acc[(2 * k + 1) & 3] = ffma2(w[2 * k + 1], hh.y, acc[(2 * k + 1) & 3]);
            }

            float2 f0 = unpack2(acc[0]), f1 = unpack2(acc[1]);
            float2 f2 = unpack2(acc[2]), f3 = unpack2(acc[3]);
            float pre = ((f0.x + f1.x) + (f2.x + f3.x))
                      + ((f0.y + f1.y) + (f2.y + f3.y)) + p_cur;

            float hn = 0.96f * hj + 0.04f * fast_tanh(pre);

            pj[(size_t)t * HID] = hn;     // coalesced 512B store (R5 order)
            hbuf[p ^ 1][j] = hn;
            hj = hn;
            p_cur = p_nxt;
            p_nxt = p_fut;
        }

        __syncthreads();                  // h[t] now visible in hbuf[p^1]

        if (j >= HID) {
            const float4* h4 = (const float4*)hbuf[p ^ 1];
            float4 hv = h4[lane];
            float q0 = hv.x * w0.x + hv.y * w0.y + hv.z * w0.z + hv.w * w0.w;
            float q1 = hv.x * w1.x + hv.y * w1.y + hv.z * w1.z + hv.w * w1.w;
            float q2 = hv.x * w2.x + hv.y * w2.y + hv.z * w2.z + hv.w * w2.w;
            #pragma unroll
            for (int off = 16; off > 0; off >>= 1) {
                q0 += __shfl_xor_sync(0xFFFFFFFFu, q0, off);
                q1 += __shfl_xor_sync(0xFFFFFFFFu, q1, off);
                q2 += __shfl_xor_sync(0xFFFFFFFFu, q2, off);
            }
            if (lane == 0) {
                po[t * OUTD + 0] = q0 + bo0;
                po[t * OUTD + 1] = q1 + bo1;
                po[t * OUTD + 2] = q2 + bo2;
            }
        }

        p ^= 1;
    }
}

extern "C" void kernel_launch(void* const* d_in, const int* in_sizes, int n_in,
                              void* d_out, int out_size)
{
    const float* x     = (const float*)d_in[0];  // [B,T,33]
    const float* W_in  = (const float*)d_in[1];  // [128,33]
    const float* b_in  = (const float*)d_in[2];  // [128]
    const float* W_rec = (const float*)d_in[3];  // [128,128]
    const float* W_out = (const float*)d_in[4];  // [3,128]
    const float* b_out = (const float*)d_in[5];  // [3]

    float* out    = (float*)d_out;
    float* pred   = out;                               // [B,T,3]
    float* hidden = out + (size_t)BATCH * TT * OUTD;   // [B,T,128]; proj then h

    // Pass 1: proj -> hidden (in place), double-buffered persistent grid
    proj_kernel<<<592, 256>>>(x, W_in, b_in, hidden);

    // Pass 2: recurrence + fused readout (1 row per CTA, 5 warps)
    rnn_recurrence_kernel<<<BATCH, 160>>>(W_rec, W_out, b_out, hidden, pred);
}

// round 14
// speedup vs baseline: 1.4211x; 1.4211x over previous
#include <cuda_runtime.h>

#define HID 128
#define INP 33
#define OUTD 3
#define TT 2000
#define BATCH 256

typedef unsigned long long u64;

// Packed fp32x2 FMA (FFMA2) — only reachable via PTX fma.rn.f32x2.
__device__ __forceinline__ u64 ffma2(u64 a, u64 b, u64 c) {
    u64 d;
    asm("fma.rn.f32x2 %0, %1, %2, %3;" : "=l"(d) : "l"(a), "l"(b), "l"(c));
    return d;
}
__device__ __forceinline__ float2 unpack2(u64 v) {
    float2 f;
    asm("mov.b64 {%0, %1}, %2;" : "=f"(f.x), "=f"(f.y) : "l"(v));
    return f;
}
__device__ __forceinline__ u64 pack2(float x, float y) {
    u64 v;
    asm("mov.b64 %0, {%1, %2};" : "=l"(v) : "f"(x), "f"(y));
    return v;
}

// Accurate tanh via __expf (MUFU): rel err ~1e-6 (tanh.approx's 6e-4 is unsafe
// over a 2000-step recurrence).
__device__ __forceinline__ float fast_tanh(float x) {
    float ax = fabsf(x);
    float e = __expf(2.0f * fminf(ax, 10.0f));
    float t = 1.0f - 2.0f / (e + 1.0f);
    return copysignf(t, x);
}

// ---------------------------------------------------------------------------
// Pass 1: input projection, in-place into the hidden output buffer.
// Double-buffered x staging: one barrier per tile; next tile's gmem loads
// overlap current tile's compute.
// ---------------------------------------------------------------------------
#define PR 32

__global__ void __launch_bounds__(256)
proj_kernel(const float* __restrict__ x,
            const float* __restrict__ W_in,
            const float* __restrict__ b_in,
            float* __restrict__ proj)
{
    __shared__ __align__(16) float xs[2][PR][34];

    const int tid  = threadIdx.x;
    const int j    = tid & 127;
    const int half = tid >> 7;

    // W_in row j -> 17 packed pairs (last = (w32, 0))
    u64 wi[17];
    {
        float wv[34];
        #pragma unroll
        for (int i = 0; i < INP; i++) wv[i] = W_in[j * INP + i];
        wv[33] = 0.0f;
        #pragma unroll
        for (int i = 0; i < 17; i++) wi[i] = pack2(wv[2 * i], wv[2 * i + 1]);
    }
    const float bj = b_in[j];

    if (tid < PR) { xs[0][tid][33] = 0.0f; xs[1][tid][33] = 0.0f; }

    const int ntiles = (BATCH * TT) / PR;   // 16000
    int tile = blockIdx.x;

    {
        const float* xsrc = x + (long)tile * PR * INP;
        for (int idx = tid; idx < PR * INP; idx += 256) {
            int r = idx / INP, i = idx - r * INP;
            xs[0][r][i] = xsrc[idx];
        }
    }
    __syncthreads();

    int buf = 0;
    while (tile < ntiles) {
        const int next = tile + gridDim.x;
        if (next < ntiles) {                       // prefetch next tile (other buf)
            const float* xsrc = x + (long)next * PR * INP;
            for (int idx = tid; idx < PR * INP; idx += 256) {
                int r = idx / INP, i = idx - r * INP;
                xs[buf ^ 1][r][i] = xsrc[idx];
            }
        }

        const long base = (long)tile * PR;
        #pragma unroll 4
        for (int rr = 0; rr < 16; rr++) {
            int r = half * 16 + rr;
            const u64* xp = (const u64*)xs[buf][r];
            u64 acc[4] = {0ull, 0ull, 0ull, 0ull};
            #pragma unroll
            for (int i = 0; i < 17; i++)
                acc[i & 3] = ffma2(wi[i], xp[i], acc[i & 3]);
            float2 f0 = unpack2(acc[0]), f1 = unpack2(acc[1]);
            float2 f2 = unpack2(acc[2]), f3 = unpack2(acc[3]);
            float s = ((f0.x + f1.x) + (f2.x + f3.x))
                    + ((f0.y + f1.y) + (f2.y + f3.y)) + bj;
            proj[(base + r) * HID + j] = s;
        }

        __syncthreads();
        buf ^= 1;
        tile = next;
    }
}

// ---------------------------------------------------------------------------
// Pass 2: serial recurrence, SPLIT-DOT: 256 threads per CTA (8 warps), one
// batch row per CTA. Partners (tid, tid^1) — same warp — each compute half of
// hidden unit j = tid>>1's 128-wide dot (32 FFMA2 + 16 broadcast LDS.128
// each), combined with one __shfl_xor(1). Same FMA/LDS issue totals as R5 but
// 4 warps/SMSP (vs 2) cover the reduce+tanh serial tail, and the per-step
// dependency chain is half as long. ONE __syncthreads per step. ~100 regs.
// ---------------------------------------------------------------------------
__global__ void __launch_bounds__(256, 2)
rnn_recurrence_kernel(const float* __restrict__ W_rec,
                      float* __restrict__ hidden /* in: proj, out: h */)
{
    __shared__ __align__(16) float hbuf[2][HID];

    const int tid  = threadIdx.x;
    const int j    = tid >> 1;        // hidden unit (each unit: 2 threads)
    const int half = tid & 1;         // which 64-wide half of the dot

    // W_rec[j, half*64 .. half*64+63] as 16 ulonglong2 -> 32 packed pairs.
    u64 w[32];
    {
        const ulonglong2* wrow =
            (const ulonglong2*)(W_rec + j * HID + half * 64);
        #pragma unroll
        for (int k = 0; k < 16; k++) {
            ulonglong2 v = wrow[k];
            w[2 * k]     = v.x;
            w[2 * k + 1] = v.y;
        }
    }

    if (half == 0) hbuf[0][j] = 0.0f;
    float hj = 0.0f;
    float* pj = hidden + (size_t)blockIdx.x * TT * HID + j;

    // proj prefetch pipeline, distance 2 (partners load same addr: broadcast).
    float p_cur = __ldg(pj);
    float p_nxt = __ldg(pj + HID);
    __syncthreads();

    int p = 0;
    for (int t = 0; t < TT; t++) {
        float p_fut = 0.0f;
        if (t + 2 < TT) p_fut = __ldg(pj + (size_t)(t + 2) * HID);

        const ulonglong2* hs = (const ulonglong2*)(hbuf[p] + half * 64);
        u64 acc[4] = {0ull, 0ull, 0ull, 0ull};

        #pragma unroll
        for (int k = 0; k < 16; k++) {
            ulonglong2 hh = hs[k];                       // 2-addr broadcast LDS.128
            acc[(2 * k)     & 3] = ffma2(w[2 * k],     hh.x, acc[(2 * k)     & 3]);
            acc[(2 * k + 1) & 3] = ffma2(w[2 * k + 1], hh.y, acc[(2 * k + 1) & 3]);
        }

        float2 f0 = unpack2(acc[0]), f1 = unpack2(acc[1]);
        float2 f2 = unpack2(acc[2]), f3 = unpack2(acc[3]);
        float s = ((f0.x + f1.x) + (f2.x + f3.x))
                + ((f0.y + f1.y) + (f2.y + f3.y));

        // Combine partner halves (adjacent lanes, same warp).
        float pre = s + __shfl_xor_sync(0xFFFFFFFFu, s, 1) + p_cur;

        float hn = 0.96f * hj + 0.04f * fast_tanh(pre);   // both halves compute

        if (half == 0) {
            pj[(size_t)t * HID] = hn;        // 64B per warp, contiguous overall
            hbuf[p ^ 1][j] = hn;
        }
        hj = hn;
        p_cur = p_nxt;
        p_nxt = p_fut;

        __syncthreads();                     // single barrier per step
        p ^= 1;
    }
}

// ---------------------------------------------------------------------------
// Pass 3: readout (exact R5 kernel, known 115 us). One warp per (b,t) row.
// ---------------------------------------------------------------------------
__global__ void readout_kernel(const float* __restrict__ hidden,
                               const float* __restrict__ W_out,
                               const float* __restrict__ b_out,
                               float* __restrict__ pred,
                               int nrows)
{
    int gwarp = (blockIdx.x * blockDim.x + threadIdx.x) >> 5;
    int lane  = threadIdx.x & 31;
    if (gwarp >= nrows) return;

    const float4* h4 = (const float4*)(hidden + (size_t)gwarp * HID);
    float4 hv = h4[lane];

    const float4* w4 = (const float4*)W_out;
    float4 w0 = __ldg(&w4[lane]);
    float4 w1 = __ldg(&w4[32 + lane]);
    float4 w2 = __ldg(&w4[64 + lane]);

    float p0 = hv.x * w0.x + hv.y * w0.y + hv.z * w0.z + hv.w * w0.w;
    float p1 = hv.x * w1.x + hv.y * w1.y + hv.z * w1.z + hv.w * w1.w;
    float p2 = hv.x * w2.x + hv.y * w2.y + hv.z * w2.z + hv.w * w2.w;

    #pragma unroll
    for (int off = 16; off > 0; off >>= 1) {
        p0 += __shfl_xor_sync(0xFFFFFFFFu, p0, off);
        p1 += __shfl_xor_sync(0xFFFFFFFFu, p1, off);
        p2 += __shfl_xor_sync(0xFFFFFFFFu, p2, off);
    }

    if (lane == 0) {
        float* o = pred + (size_t)gwarp * OUTD;
        o[0] = p0 + b_out[0];
        o[1] = p1 + b_out[1];
        o[2] = p2 + b_out[2];
    }
}

extern "C" void kernel_launch(void* const* d_in, const int* in_sizes, int n_in,
                              void* d_out, int out_size)
{
    const float* x     = (const float*)d_in[0];  // [B,T,33]
    const float* W_in  = (const float*)d_in[1];  // [128,33]
    const float* b_in  = (const float*)d_in[2];  // [128]
    const float* W_rec = (const float*)d_in[3];  // [128,128]
    const float* W_out = (const float*)d_in[4];  // [3,128]
    const float* b_out = (const float*)d_in[5];  // [3]

    float* out    = (float*)d_out;
    float* pred   = out;                               // [B,T,3]
    float* hidden = out + (size_t)BATCH * TT * OUTD;   // [B,T,128]; proj then h

    // Pass 1: proj -> hidden (in place), double-buffered persistent grid
    proj_kernel<<<592, 256>>>(x, W_in, b_in, hidden);

    // Pass 2: split-dot recurrence (1 row/CTA, 8 warps, 2 CTAs/SM)
    rnn_recurrence_kernel<<<BATCH, 256>>>(W_rec, hidden);

    // Pass 3: readout (R5 exact)
    int nrows = BATCH * TT;                            // 512000
    readout_kernel<<<(nrows + 7) / 8, 256>>>(hidden, W_out, b_out, pred, nrows);
}

// round 15
// speedup vs baseline: 1.9715x; 1.3873x over previous
#include <cuda_runtime.h>

#define HID 128
#define INP 33
#define OUTD 3
#define TT 2000
#define BATCH 256

typedef unsigned long long u64;

// Packed fp32x2 FMA (FFMA2) — only reachable via PTX fma.rn.f32x2.
__device__ __forceinline__ u64 ffma2(u64 a, u64 b, u64 c) {
    u64 d;
    asm("fma.rn.f32x2 %0, %1, %2, %3;" : "=l"(d) : "l"(a), "l"(b), "l"(c));
    return d;
}
__device__ __forceinline__ u64 fadd2(u64 a, u64 b) {
    u64 d;
    asm("add.rn.f32x2 %0, %1, %2;" : "=l"(d) : "l"(a), "l"(b));
    return d;
}
__device__ __forceinline__ float2 unpack2(u64 v) {
    float2 f;
    asm("mov.b64 {%0, %1}, %2;" : "=f"(f.x), "=f"(f.y) : "l"(v));
    return f;
}
__device__ __forceinline__ u64 pack2(float x, float y) {
    u64 v;
    asm("mov.b64 %0, {%1, %2};" : "=l"(v) : "f"(x), "f"(y));
    return v;
}

// Accurate tanh via __expf (MUFU): rel err ~1e-6 (tanh.approx's 6e-4 is unsafe
// over a 2000-step recurrence).
__device__ __forceinline__ float fast_tanh(float x) {
    float ax = fabsf(x);
    float e = __expf(2.0f * fminf(ax, 10.0f));
    float t = 1.0f - 2.0f / (e + 1.0f);
    return copysignf(t, x);
}

// ---------------------------------------------------------------------------
// Pass 1: input projection, in-place into the hidden output buffer.
// Double-buffered x staging (measured 176 us in R14): one barrier per tile,
// next tile's gmem loads overlap current tile's compute.
// ---------------------------------------------------------------------------
#define PR 32

__global__ void __launch_bounds__(256)
proj_kernel(const float* __restrict__ x,
            const float* __restrict__ W_in,
            const float* __restrict__ b_in,
            float* __restrict__ proj)
{
    __shared__ __align__(16) float xs[2][PR][34];

    const int tid  = threadIdx.x;
    const int j    = tid & 127;
    const int half = tid >> 7;

    // W_in row j -> 17 packed pairs (last = (w32, 0))
    u64 wi[17];
    {
        float wv[34];
        #pragma unroll
        for (int i = 0; i < INP; i++) wv[i] = W_in[j * INP + i];
        wv[33] = 0.0f;
        #pragma unroll
        for (int i = 0; i < 17; i++) wi[i] = pack2(wv[2 * i], wv[2 * i + 1]);
    }
    const float bj = b_in[j];

    if (tid < PR) { xs[0][tid][33] = 0.0f; xs[1][tid][33] = 0.0f; }

    const int ntiles = (BATCH * TT) / PR;   // 16000
    int tile = blockIdx.x;

    {
        const float* xsrc = x + (long)tile * PR * INP;
        for (int idx = tid; idx < PR * INP; idx += 256) {
            int r = idx / INP, i = idx - r * INP;
            xs[0][r][i] = xsrc[idx];
        }
    }
    __syncthreads();

    int buf = 0;
    while (tile < ntiles) {
        const int next = tile + gridDim.x;
        if (next < ntiles) {                       // prefetch next tile (other buf)
            const float* xsrc = x + (long)next * PR * INP;
            for (int idx = tid; idx < PR * INP; idx += 256) {
                int r = idx / INP, i = idx - r * INP;
                xs[buf ^ 1][r][i] = xsrc[idx];
            }
        }

        const long base = (long)tile * PR;
        #pragma unroll 4
        for (int rr = 0; rr < 16; rr++) {
            int r = half * 16 + rr;
            const u64* xp = (const u64*)xs[buf][r];
            u64 acc[4] = {0ull, 0ull, 0ull, 0ull};
            #pragma unroll
            for (int i = 0; i < 17; i++)
                acc[i & 3] = ffma2(wi[i], xp[i], acc[i & 3]);
            u64 s01 = fadd2(acc[0], acc[1]);
            u64 s23 = fadd2(acc[2], acc[3]);
            float2 sf = unpack2(fadd2(s01, s23));
            proj[(base + r) * HID + j] = sf.x + sf.y + bj;
        }

        __syncthreads();
        buf ^= 1;
        tile = next;
    }
}

// ---------------------------------------------------------------------------
// Pass 2: serial recurrence — R5's measured-best core (1 batch row per CTA,
// 128 threads, 2 CTAs/SM -> 2 warps/SMSP), with three tail tweaks:
//   (1) acc seeded with p_cur (kills a serial FADD),
//   (2) packed f32x2 reduce tree (serial depth 7 -> 4),
//   (3) gmem h-store moved after the barrier (shorter pre-barrier tail; the
//       STG overlaps the next step's LDS ramp).
// ---------------------------------------------------------------------------
__global__ void __launch_bounds__(128, 2)
rnn_recurrence_kernel(const float* __restrict__ W_rec,
                      float* __restrict__ hidden /* in: proj, out: h */)
{
    __shared__ __align__(16) float hbuf[2][HID];

    const int j = threadIdx.x;
    const int b = blockIdx.x;

    // W_rec row j as 64 packed pairs (rows are 512B-aligned).
    u64 w[64];
    {
        const ulonglong2* wrow = (const ulonglong2*)(W_rec + j * HID);
        #pragma unroll
        for (int k = 0; k < 32; k++) {
            ulonglong2 v = wrow[k];
            w[2 * k]     = v.x;
            w[2 * k + 1] = v.y;
        }
    }

    hbuf[0][j] = 0.0f;
    float hj = 0.0f;
    float* pj = hidden + (size_t)b * TT * HID + j;

    // proj prefetch pipeline, distance 2.
    float p_cur = __ldg(pj);
    float p_nxt = __ldg(pj + HID);
    __syncthreads();

    int p = 0;
    for (int t = 0; t < TT; t++) {
        float p_fut = 0.0f;
        if (t + 2 < TT) p_fut = __ldg(pj + (size_t)(t + 2) * HID);

        const ulonglong2* hs = (const ulonglong2*)hbuf[p];
        u64 acc[4] = {pack2(p_cur, 0.0f), 0ull, 0ull, 0ull};   // (1) seed

        #pragma unroll
        for (int k = 0; k < 32; k++) {
            ulonglong2 hh = hs[k];                       // broadcast LDS.128
            acc[(2 * k)     & 3] = ffma2(w[2 * k],     hh.x, acc[(2 * k)     & 3]);
            acc[(2 * k + 1) & 3] = ffma2(w[2 * k + 1], hh.y, acc[(2 * k + 1) & 3]);
        }

        // (2) packed reduce: depth = 2 packed adds + unpack + 1 fadd
        u64 s01 = fadd2(acc[0], acc[1]);
        u64 s23 = fadd2(acc[2], acc[3]);
        float2 sf = unpack2(fadd2(s01, s23));
        float pre = sf.x + sf.y;

        float hn = 0.96f * hj + 0.04f * fast_tanh(pre);

        hbuf[p ^ 1][j] = hn;
        __syncthreads();                  // (3) barrier before the gmem store

        pj[(size_t)t * HID] = hn;         // coalesced 512B store, overlaps next LDS

        hj = hn;
        p_cur = p_nxt;
        p_nxt = p_fut;
        p ^= 1;
    }
}

// ---------------------------------------------------------------------------
// Pass 3: readout (R5 exact, measured 115 us). One warp per (b,t) row.
// ---------------------------------------------------------------------------
__global__ void readout_kernel(const float* __restrict__ hidden,
                               const float* __restrict__ W_out,
                               const float* __restrict__ b_out,
                               float* __restrict__ pred,
                               int nrows)
{
    int gwarp = (blockIdx.x * blockDim.x + threadIdx.x) >> 5;
    int lane  = threadIdx.x & 31;
    if (gwarp >= nrows) return;

    const float4* h4 = (const float4*)(hidden + (size_t)gwarp * HID);
    float4 hv = h4[lane];

    const float4* w4 = (const float4*)W_out;
    float4 w0 = __ldg(&w4[lane]);
    float4 w1 = __ldg(&w4[32 + lane]);
    float4 w2 = __ldg(&w4[64 + lane]);

    float p0 = hv.x * w0.x + hv.y * w0.y + hv.z * w0.z + hv.w * w0.w;
    float p1 = hv.x * w1.x + hv.y * w1.y + hv.z * w1.z + hv.w * w1.w;
    float p2 = hv.x * w2.x + hv.y * w2.y + hv.z * w2.z + hv.w * w2.w;

    #pragma unroll
    for (int off = 16; off > 0; off >>= 1) {
        p0 += __shfl_xor_sync(0xFFFFFFFFu, p0, off);
        p1 += __shfl_xor_sync(0xFFFFFFFFu, p1, off);
        p2 += __shfl_xor_sync(0xFFFFFFFFu, p2, off);
    }

    if (lane == 0) {
        float* o = pred + (size_t)gwarp * OUTD;
        o[0] = p0 + b_out[0];
        o[1] = p1 + b_out[1];
        o[2] = p2 + b_out[2];
    }
}

extern "C" void kernel_launch(void* const* d_in, const int* in_sizes, int n_in,
                              void* d_out, int out_size)
{
    const float* x     = (const float*)d_in[0];  // [B,T,33]
    const float* W_in  = (const float*)d_in[1];  // [128,33]
    const float* b_in  = (const float*)d_in[2];  // [128]
    const float* W_rec = (const float*)d_in[3];  // [128,128]
    const float* W_out = (const float*)d_in[4];  // [3,128]
    const float* b_out = (const float*)d_in[5];  // [3]

    float* out    = (float*)d_out;
    float* pred   = out;                               // [B,T,3]
    float* hidden = out + (size_t)BATCH * TT * OUTD;   // [B,T,128]; proj then h

    // Pass 1: proj -> hidden (in place), double-buffered persistent grid
    proj_kernel<<<592, 256>>>(x, W_in, b_in, hidden);

    // Pass 2: R5-core recurrence with tail tweaks (1 row/CTA, 2 CTAs/SM)
    rnn_recurrence_kernel<<<BATCH, 128>>>(W_rec, hidden);

    // Pass 3: readout (R5 exact)
    int nrows = BATCH * TT;                            // 512000
    readout_kernel<<<(nrows + 7) / 8, 256>>>(hidden, W_out, b_out, pred, nrows);
}